// round 12
// baseline (speedup 1.0000x reference)
#include <cuda_runtime.h>
#include <cuda_bf16.h>
#include <mma.h>
#include <cstdint>

using namespace nvcuda;

#define T_SEQ 512
#define B_SZ  256
#define IN_D  64
#define H_D   128
#define G4    512
#define TB    (T_SEQ * B_SZ)
#define TC    64                      // timesteps per chunk
#define NCH   8                       // chunks
#define CHROWS (TC * B_SZ)            // 16384 rows per chunk

// ---- scratch (__device__ globals) ----
__device__ float g_bufA[TB * H_D];                    // dummy f32 sink
__device__ float g_preb[5ULL * TB * G4];              // per-layer pre
__device__ __nv_bfloat16 g_actH[5ULL * TB * H_D];     // per-layer h hi
__device__ __nv_bfloat16 g_actL[5ULL * TB * H_D];     // per-layer h lo
__device__ __nv_bfloat16 g_xh[TB * IN_D];             // layer-0 input hi
__device__ __nv_bfloat16 g_xl[TB * IN_D];
__device__ __nv_bfloat16 g_wh[5 * H_D * G4];          // per-layer W^T hi
__device__ __nv_bfloat16 g_wl[5 * H_D * G4];
__device__ float g_hst[5 * B_SZ * H_D];               // h carry between chunks
__device__ float g_cst[5 * B_SZ * H_D];               // c carry

// ---------------- helpers ----------------
__device__ __forceinline__ void fma2(unsigned long long &acc,
                                     unsigned long long a, unsigned long long b) {
    asm("fma.rn.f32x2 %0, %1, %2, %3;" : "=l"(acc) : "l"(a), "l"(b), "l"(acc));
}
__device__ __forceinline__ unsigned long long pack2(float lo, float hi) {
    unsigned long long r;
    asm("mov.b64 %0, {%1, %2};" : "=l"(r) : "f"(lo), "f"(hi));
    return r;
}
__device__ __forceinline__ float sum2(unsigned long long v) {
    float lo, hi;
    asm("mov.b64 {%0, %1}, %2;" : "=f"(lo), "=f"(hi) : "l"(v));
    return lo + hi;
}
__device__ __forceinline__ float fsig(float x) {
    return __fdividef(1.0f, 1.0f + __expf(-x));
}
__device__ __forceinline__ float ftanh(float x) {
    return __fdividef(2.0f, 1.0f + __expf(-2.0f * x)) - 1.0f;
}
__device__ __forceinline__ void split2(float a, float b,
                                       __nv_bfloat162 &h, __nv_bfloat162 &l) {
    const __nv_bfloat16 ha = __float2bfloat16_rn(a);
    const __nv_bfloat16 hb = __float2bfloat16_rn(b);
    h.x = ha; h.y = hb;
    l.x = __float2bfloat16_rn(a - __bfloat162float(ha));
    l.y = __float2bfloat16_rn(b - __bfloat162float(hb));
}

// ============================================================================
__global__ void xconvert(const float* __restrict__ x,
                         __nv_bfloat16* __restrict__ xh,
                         __nv_bfloat16* __restrict__ xl, int n4) {
    const int i = blockIdx.x * blockDim.x + threadIdx.x;
    if (i >= n4) return;
    const float4 v = ((const float4*)x)[i];
    __nv_bfloat162 h0, l0, h1, l1;
    split2(v.x, v.y, h0, l0);
    split2(v.z, v.w, h1, l1);
    ((__nv_bfloat162*)xh)[2 * i]     = h0;
    ((__nv_bfloat162*)xh)[2 * i + 1] = h1;
    ((__nv_bfloat162*)xl)[2 * i]     = l0;
    ((__nv_bfloat162*)xl)[2 * i + 1] = l1;
}

__global__ void wconvert(const float* __restrict__ W,
                         __nv_bfloat16* __restrict__ wh,
                         __nv_bfloat16* __restrict__ wl, int K) {
    const int e = blockIdx.x * blockDim.x + threadIdx.x;
    if (e >= K * G4) return;
    const int k = e >> 9, n = e & 511;
    const float v = W[(size_t)n * K + k];
    const __nv_bfloat16 h = __float2bfloat16_rn(v);
    wh[e] = h;
    wl[e] = __float2bfloat16_rn(v - __bfloat162float(h));
}

// ============================================================================
// pregemm (R10/R11-measured-good), chunked: caller offsets base pointers.
// grid = (CHROWS/64)*4 = 1024. Tensor-pipe only (no FMA contention with rec).
// ============================================================================
template<int K>
__global__ void __launch_bounds__(256, 2)
pregemm(const __nv_bfloat16* __restrict__ Ahg,   // [rows][K]
        const __nv_bfloat16* __restrict__ Alg,
        const __nv_bfloat16* __restrict__ Bhg,   // [K][512]
        const __nv_bfloat16* __restrict__ Blg,
        const float* __restrict__ bih, const float* __restrict__ bhh,
        float* __restrict__ pre)
{
    constexpr int AS = K + 8;
    constexpr int BS = 128 + 8;
    extern __shared__ __align__(256) char smp[];
    float* bias = (float*)smp;
    __nv_bfloat16* Ah = (__nv_bfloat16*)(smp + 512);
    __nv_bfloat16* Al = Ah + 64 * AS;
    __nv_bfloat16* Bh = Al + 64 * AS;
    __nv_bfloat16* Bl = Bh + K * BS;
    float* Dsm = (float*)(smp + 512);

    const int tid = threadIdx.x;
    const int wid = tid >> 5;
    const int m0 = (int)(blockIdx.x >> 2) * 64;
    const int n0 = (int)(blockIdx.x & 3) * 128;

    if (tid < 128) bias[tid] = bih[n0 + tid] + bhh[n0 + tid];

    for (int i = tid; i < 64 * K / 8; i += 256) {
        const int r = i / (K / 8), c8 = (i % (K / 8)) * 8;
        *(uint4*)(Ah + r * AS + c8) =
            *(const uint4*)(Ahg + (size_t)(m0 + r) * K + c8);
        *(uint4*)(Al + r * AS + c8) =
            *(const uint4*)(Alg + (size_t)(m0 + r) * K + c8);
    }
    for (int i = tid; i < K * 16; i += 256) {
        const int k = i >> 4, c8 = (i & 15) * 8;
        *(uint4*)(Bh + k * BS + c8) =
            *(const uint4*)(Bhg + (size_t)k * G4 + n0 + c8);
        *(uint4*)(Bl + k * BS + c8) =
            *(const uint4*)(Blg + (size_t)k * G4 + n0 + c8);
    }
    __syncthreads();

    const int wm = wid >> 1;
    const int wn = wid & 1;

    wmma::fragment<wmma::accumulator, 16, 16, 16, float> acc[4];
#pragma unroll
    for (int ni = 0; ni < 4; ni++) wmma::fill_fragment(acc[ni], 0.0f);

#pragma unroll
    for (int ks = 0; ks < K / 16; ks++) {
        wmma::fragment<wmma::matrix_a, 16, 16, 16, __nv_bfloat16,
                       wmma::row_major> ah, al;
        wmma::load_matrix_sync(ah, Ah + (wm * 16) * AS + ks * 16, AS);
        wmma::load_matrix_sync(al, Al + (wm * 16) * AS + ks * 16, AS);
#pragma unroll
        for (int ni = 0; ni < 4; ni++) {
            wmma::fragment<wmma::matrix_b, 16, 16, 16, __nv_bfloat16,
                           wmma::row_major> bhf, blf;
            wmma::load_matrix_sync(bhf,
                Bh + ks * 16 * BS + wn * 64 + ni * 16, BS);
            wmma::load_matrix_sync(blf,
                Bl + ks * 16 * BS + wn * 64 + ni * 16, BS);
            wmma::mma_sync(acc[ni], ah, bhf, acc[ni]);
            wmma::mma_sync(acc[ni], ah, blf, acc[ni]);
            wmma::mma_sync(acc[ni], al, bhf, acc[ni]);
        }
    }
    __syncthreads();

#pragma unroll
    for (int ni = 0; ni < 4; ni++)
        wmma::store_matrix_sync(
            Dsm + (wm * 16) * 128 + wn * 64 + ni * 16,
            acc[ni], 128, wmma::mem_row_major);
    __syncthreads();

    for (int i = tid; i < 64 * 32; i += 256) {
        const int r = i >> 5, c4 = (i & 31) * 4;
        float4 v = *(const float4*)(Dsm + r * 128 + c4);
        v.x += bias[c4];     v.y += bias[c4 + 1];
        v.z += bias[c4 + 2]; v.w += bias[c4 + 3];
        *(float4*)(pre + (size_t)(m0 + r) * G4 + n0 + c4) = v;
    }
}

// ============================================================================
// lstm_rec chunk (R11 dot/sync structure, validated): TC steps, h/c carried
// in global between chunks. first==1 -> zero initial state.
// ============================================================================
__global__ void __launch_bounds__(256, 2) __cluster_dims__(4, 1, 1)
lstm_rec(const float* __restrict__ pre,   // chunk base [TC,B,512]
         float* __restrict__ out,         // chunk base [TC,B,128]
         const float* __restrict__ Whh,   // [512,128]
         __nv_bfloat16* __restrict__ gh,  // chunk base h hi
         __nv_bfloat16* __restrict__ gl,  // chunk base h lo
         float* __restrict__ hst,         // [B,128] carry
         float* __restrict__ cst,         // [B,128] carry
         int first)
{
    __shared__ float gbuf[8][4][128];
    __shared__ __align__(16) float hs[2][4][128];

    const int tid = threadIdx.x, lane = tid & 31, w = tid >> 5;
    uint32_t rank;
    asm("mov.u32 %0, %%cluster_ctarank;" : "=r"(rank));
    const int sl = (w + 2 * (int)rank) & 7;
    const int k0 = sl * 16;
    const bool own = (w < 2);
    const int b0 = (blockIdx.x >> 2) * 4;

    unsigned long long Wr[4][8];
#pragma unroll
    for (int g = 0; g < 4; g++) {
        const int grow = g * H_D + (int)rank * 32 + lane;
#pragma unroll
        for (int i = 0; i < 8; i++)
            Wr[g][i] = pack2(Whh[grow * H_D + k0 + 2 * i],
                             Whh[grow * H_D + k0 + 2 * i + 1]);
    }

    const int ob = tid >> 5, oj = tid & 31;
    const int jglob = (int)rank * 32 + oj;
    float c_state = 0.0f;
    const float* pre_p = pre + ((size_t)b0 + ob) * G4 + jglob;
    float* out_p = out + ((size_t)b0 + ob) * H_D + jglob;
    __nv_bfloat16* gh_p = gh + ((size_t)b0 + ob) * H_D + jglob;
    __nv_bfloat16* gl_p = gl + ((size_t)b0 + ob) * H_D + jglob;

    if (first) {
        for (int i = tid; i < 4 * H_D; i += 256) hs[0][i >> 7][i & 127] = 0.0f;
    } else {
        for (int i = tid; i < 4 * H_D; i += 256)
            hs[0][i >> 7][i & 127] = hst[(size_t)(b0 + (i >> 7)) * H_D + (i & 127)];
        if (tid < 128) c_state = cst[(size_t)(b0 + ob) * H_D + jglob];
    }
    __syncthreads();
    asm volatile("barrier.cluster.arrive.aligned;" ::: "memory");

    for (int tl = 0; tl < TC; tl++) {
        const int cur = tl & 1, nxt = cur ^ 1;
        const bool more = (tl + 1 < TC);

        float p0, p1, p2, p3;
        if (tid < 128) {
            p0 = pre_p[0];   p1 = pre_p[128];
            p2 = pre_p[256]; p3 = pre_p[384];
            pre_p += (size_t)B_SZ * G4;
        }

        unsigned long long acc[4][4];
#pragma unroll
        for (int g = 0; g < 4; g++)
#pragma unroll
            for (int b = 0; b < 4; b++) acc[g][b] = 0ull;

        if (own) {   // local h columns (ordered by trailing __syncthreads)
#pragma unroll
            for (int kk = 0; kk < 4; kk++) {
                ulonglong2 v[4];
#pragma unroll
                for (int b = 0; b < 4; b++)
                    v[b] = *(const ulonglong2*)(&hs[cur][b][k0 + 4 * kk]);
#pragma unroll
                for (int g = 0; g < 4; g++)
#pragma unroll
                    for (int b = 0; b < 4; b++) {
                        fma2(acc[g][b], v[b].x, Wr[g][2 * kk]);
                        fma2(acc[g][b], v[b].y, Wr[g][2 * kk + 1]);
                    }
            }
#pragma unroll
            for (int g = 0; g < 4; g++)
#pragma unroll
                for (int b = 0; b < 4; b++)
                    gbuf[sl][b][g * 32 + lane] = sum2(acc[g][b]);
        }

        asm volatile("barrier.cluster.wait.aligned;" ::: "memory");

        if (!own) {  // peer h columns (published via DSMEM before the barrier)
#pragma unroll
            for (int kk = 0; kk < 4; kk++) {
                ulonglong2 v[4];
#pragma unroll
                for (int b = 0; b < 4; b++)
                    v[b] = *(const ulonglong2*)(&hs[cur][b][k0 + 4 * kk]);
#pragma unroll
                for (int g = 0; g < 4; g++)
#pragma unroll
                    for (int b = 0; b < 4; b++) {
                        fma2(acc[g][b], v[b].x, Wr[g][2 * kk]);
                        fma2(acc[g][b], v[b].y, Wr[g][2 * kk + 1]);
                    }
            }
#pragma unroll
            for (int g = 0; g < 4; g++)
#pragma unroll
                for (int b = 0; b < 4; b++)
                    gbuf[sl][b][g * 32 + lane] = sum2(acc[g][b]);
        }

        __syncthreads();

        if (tid < 128) {
            float gv0 = p0, gv1 = p1, gv2 = p2, gv3 = p3;
#pragma unroll
            for (int q = 0; q < 8; q++) {
                gv0 += gbuf[q][ob][oj];
                gv1 += gbuf[q][ob][32 + oj];
                gv2 += gbuf[q][ob][64 + oj];
                gv3 += gbuf[q][ob][96 + oj];
            }
            const float ig = fsig(gv0), fg = fsig(gv1);
            const float gg = ftanh(gv2), og = fsig(gv3);
            c_state = fg * c_state + ig * gg;
            const float h = og * ftanh(c_state);

            if (more) {
                float* hp = &hs[nxt][ob][jglob];
                *hp = h;
                const uint32_t la = (uint32_t)__cvta_generic_to_shared(hp);
#pragma unroll
                for (int pr = 0; pr < 4; pr++)
                    if (pr != (int)rank)
                        asm volatile("{ .reg .b32 ra;\n\t"
                            "mapa.shared::cluster.u32 ra, %0, %1;\n\t"
                            "st.shared::cluster.f32 [ra], %2; }"
                            :: "r"(la), "r"(pr), "f"(h) : "memory");
            } else {
                hst[(size_t)(b0 + ob) * H_D + jglob] = h;
                cst[(size_t)(b0 + ob) * H_D + jglob] = c_state;
            }
            *out_p = h;
            out_p += (size_t)B_SZ * H_D;
            const __nv_bfloat16 hh = __float2bfloat16_rn(h);
            *gh_p = hh;
            *gl_p = __float2bfloat16_rn(h - __bfloat162float(hh));
            gh_p += (size_t)B_SZ * H_D;
            gl_p += (size_t)B_SZ * H_D;
        }

        if (more)
            asm volatile("barrier.cluster.arrive.aligned;" ::: "memory");
        __syncthreads();
    }
}

// ============================================================================
// stream/event DAG (created once; capture-legal fork/join each call)
// ============================================================================
struct DagRes {
    cudaStream_t ls[5], lp[5];
    cudaEvent_t fork, evP[5][NCH], evR[5][NCH], tail[10];
    DagRes() {
        for (int l = 0; l < 5; l++) {
            cudaStreamCreateWithFlags(&ls[l], cudaStreamNonBlocking);
            cudaStreamCreateWithFlags(&lp[l], cudaStreamNonBlocking);
        }
        cudaEventCreateWithFlags(&fork, cudaEventDisableTiming);
        for (int l = 0; l < 5; l++)
            for (int c = 0; c < NCH; c++) {
                cudaEventCreateWithFlags(&evP[l][c], cudaEventDisableTiming);
                cudaEventCreateWithFlags(&evR[l][c], cudaEventDisableTiming);
            }
        for (int i = 0; i < 10; i++)
            cudaEventCreateWithFlags(&tail[i], cudaEventDisableTiming);
    }
};
static DagRes g_dag;   // created at static init (before any mem checkpoint)

extern "C" void kernel_launch(void* const* d_in, const int* in_sizes, int n_in,
                              void* d_out, int out_size) {
    const float* x     = (const float*)d_in[0];
    const float* Wih0  = (const float*)d_in[1];
    const float* Wrest = (const float*)d_in[2];
    const float* Whh   = (const float*)d_in[3];
    const float* bih   = (const float*)d_in[4];
    const float* bhh   = (const float*)d_in[5];
    float* out = (float*)d_out;

    float *bufA, *preb, *hst, *cst;
    __nv_bfloat16 *actH, *actL, *xh, *xl, *wh, *wl;
    cudaGetSymbolAddress((void**)&bufA, g_bufA);
    cudaGetSymbolAddress((void**)&preb, g_preb);
    cudaGetSymbolAddress((void**)&actH, g_actH);
    cudaGetSymbolAddress((void**)&actL, g_actL);
    cudaGetSymbolAddress((void**)&xh, g_xh);
    cudaGetSymbolAddress((void**)&xl, g_xl);
    cudaGetSymbolAddress((void**)&wh, g_wh);
    cudaGetSymbolAddress((void**)&wl, g_wl);
    cudaGetSymbolAddress((void**)&hst, g_hst);
    cudaGetSymbolAddress((void**)&cst, g_cst);

    const int SP64  = 512 + 64 * 72  * 2 * 2 + 64  * 136 * 2 * 2;  //  53760
    const int SP128 = 512 + 64 * 136 * 2 * 2 + 128 * 136 * 2 * 2;  // 104960
    cudaFuncSetAttribute(pregemm<64>,
        cudaFuncAttributeMaxDynamicSharedMemorySize, SP64);
    cudaFuncSetAttribute(pregemm<128>,
        cudaFuncAttributeMaxDynamicSharedMemorySize, SP128);

    DagRes& D = g_dag;

    // ---- upfront conversions on the capture (legacy) stream ----
    xconvert<<<TB * IN_D / 4 / 256, 256>>>(x, xh, xl, TB * IN_D / 4);
    wconvert<<<64 * G4 / 256, 256>>>(Wih0, wh, wl, 64);
    for (int l = 1; l < 5; l++)
        wconvert<<<128 * G4 / 256, 256>>>(
            Wrest + (size_t)(l - 1) * G4 * H_D,
            wh + (size_t)l * H_D * G4, wl + (size_t)l * H_D * G4, 128);

    cudaEventRecord(D.fork, 0);
    for (int l = 0; l < 5; l++) {
        cudaStreamWaitEvent(D.lp[l], D.fork, 0);
        cudaStreamWaitEvent(D.ls[l], D.fork, 0);
    }

    // ---- pipelined layer-chunk DAG ----
    for (int c = 0; c < NCH; c++) {
        for (int l = 0; l < 5; l++) {
            const size_t rowoff = (size_t)c * CHROWS;           // rows
            float* pre_c = preb + ((size_t)l * TB + rowoff) * G4;

            // pregemm(l, c) on lp[l]; needs rec(l-1, c)
            if (l > 0) cudaStreamWaitEvent(D.lp[l], D.evR[l - 1][c], 0);
            if (l == 0) {
                pregemm<64><<<1024, 256, SP64, D.lp[0]>>>(
                    xh + rowoff * IN_D, xl + rowoff * IN_D,
                    wh, wl, bih, bhh, pre_c);
            } else {
                const size_t aoff = ((size_t)(l - 1) * TB + rowoff) * H_D;
                pregemm<128><<<1024, 256, SP128, D.lp[l]>>>(
                    actH + aoff, actL + aoff,
                    wh + (size_t)l * H_D * G4, wl + (size_t)l * H_D * G4,
                    bih + (size_t)l * G4, bhh + (size_t)l * G4, pre_c);
            }
            cudaEventRecord(D.evP[l][c], D.lp[l]);

            // lstm_rec(l, c) on ls[l]; after pre(l,c) and rec(l,c-1)
            cudaStreamWaitEvent(D.ls[l], D.evP[l][c], 0);
            float* out_c = (l == 4) ? out + rowoff * H_D
                                    : bufA + rowoff * H_D;
            const size_t goff = ((size_t)l * TB + rowoff) * H_D;
            lstm_rec<<<256, 256, 0, D.ls[l]>>>(
                pre_c, out_c, Whh + (size_t)l * G4 * H_D,
                actH + goff, actL + goff,
                hst + (size_t)l * B_SZ * H_D, cst + (size_t)l * B_SZ * H_D,
                (c == 0) ? 1 : 0);
            cudaEventRecord(D.evR[l][c], D.ls[l]);
        }
    }

    // ---- join all side streams back to the capture stream ----
    for (int l = 0; l < 5; l++) {
        cudaEventRecord(D.tail[l], D.ls[l]);
        cudaStreamWaitEvent(0, D.tail[l], 0);
        cudaEventRecord(D.tail[5 + l], D.lp[l]);
        cudaStreamWaitEvent(0, D.tail[5 + l], 0);
    }
}

// round 13
// speedup vs baseline: 1.3078x; 1.3078x over previous
#include <cuda_runtime.h>
#include <cuda_bf16.h>
#include <mma.h>
#include <cstdint>

using namespace nvcuda;

#define T_SEQ 512
#define B_SZ  256
#define IN_D  64
#define H_D   128
#define G4    512
#define TB    (T_SEQ * B_SZ)
#define TC    64                      // timesteps per chunk
#define NCH   8                       // chunks
#define CHROWS (TC * B_SZ)            // 16384 rows per chunk

// ---- scratch (__device__ globals) ----
__device__ float g_bufA[TB * H_D];                    // f32 sink
__device__ float g_preb[5ULL * TB * G4];              // per-layer pre
__device__ __nv_bfloat16 g_actH[5ULL * TB * H_D];     // per-layer h hi
__device__ __nv_bfloat16 g_actL[5ULL * TB * H_D];     // per-layer h lo
__device__ __nv_bfloat16 g_xh[TB * IN_D];
__device__ __nv_bfloat16 g_xl[TB * IN_D];
__device__ __nv_bfloat16 g_wh[5 * H_D * G4];          // per-layer W^T hi
__device__ __nv_bfloat16 g_wl[5 * H_D * G4];
__device__ float g_hst[5 * B_SZ * H_D];               // h carry
__device__ float g_cst[5 * B_SZ * H_D];               // c carry

// ---------------- helpers ----------------
__device__ __forceinline__ void fma2(unsigned long long &acc,
                                     unsigned long long a, unsigned long long b) {
    asm("fma.rn.f32x2 %0, %1, %2, %3;" : "=l"(acc) : "l"(a), "l"(b), "l"(acc));
}
__device__ __forceinline__ unsigned long long pack2(float lo, float hi) {
    unsigned long long r;
    asm("mov.b64 %0, {%1, %2};" : "=l"(r) : "f"(lo), "f"(hi));
    return r;
}
__device__ __forceinline__ float sum2(unsigned long long v) {
    float lo, hi;
    asm("mov.b64 {%0, %1}, %2;" : "=f"(lo), "=f"(hi) : "l"(v));
    return lo + hi;
}
__device__ __forceinline__ float fsig(float x) {
    return __fdividef(1.0f, 1.0f + __expf(-x));
}
__device__ __forceinline__ float ftanh(float x) {
    return __fdividef(2.0f, 1.0f + __expf(-2.0f * x)) - 1.0f;
}
__device__ __forceinline__ void split2(float a, float b,
                                       __nv_bfloat162 &h, __nv_bfloat162 &l) {
    const __nv_bfloat16 ha = __float2bfloat16_rn(a);
    const __nv_bfloat16 hb = __float2bfloat16_rn(b);
    h.x = ha; h.y = hb;
    l.x = __float2bfloat16_rn(a - __bfloat162float(ha));
    l.y = __float2bfloat16_rn(b - __bfloat162float(hb));
}

// ============================================================================
__global__ void xconvert(const float* __restrict__ x,
                         __nv_bfloat16* __restrict__ xh,
                         __nv_bfloat16* __restrict__ xl, int n4) {
    const int i = blockIdx.x * blockDim.x + threadIdx.x;
    if (i >= n4) return;
    const float4 v = ((const float4*)x)[i];
    __nv_bfloat162 h0, l0, h1, l1;
    split2(v.x, v.y, h0, l0);
    split2(v.z, v.w, h1, l1);
    ((__nv_bfloat162*)xh)[2 * i]     = h0;
    ((__nv_bfloat162*)xh)[2 * i + 1] = h1;
    ((__nv_bfloat162*)xl)[2 * i]     = l0;
    ((__nv_bfloat162*)xl)[2 * i + 1] = l1;
}

__global__ void wconvert(const float* __restrict__ W,
                         __nv_bfloat16* __restrict__ wh,
                         __nv_bfloat16* __restrict__ wl, int K) {
    const int e = blockIdx.x * blockDim.x + threadIdx.x;
    if (e >= K * G4) return;
    const int k = e >> 9, n = e & 511;
    const float v = W[(size_t)n * K + k];
    const __nv_bfloat16 h = __float2bfloat16_rn(v);
    wh[e] = h;
    wl[e] = __float2bfloat16_rn(v - __bfloat162float(h));
}

// ============================================================================
// pregemm (measured-good), chunked.
// ============================================================================
template<int K>
__global__ void __launch_bounds__(256, 2)
pregemm(const __nv_bfloat16* __restrict__ Ahg,
        const __nv_bfloat16* __restrict__ Alg,
        const __nv_bfloat16* __restrict__ Bhg,
        const __nv_bfloat16* __restrict__ Blg,
        const float* __restrict__ bih, const float* __restrict__ bhh,
        float* __restrict__ pre)
{
    constexpr int AS = K + 8;
    constexpr int BS = 128 + 8;
    extern __shared__ __align__(256) char smp[];
    float* bias = (float*)smp;
    __nv_bfloat16* Ah = (__nv_bfloat16*)(smp + 512);
    __nv_bfloat16* Al = Ah + 64 * AS;
    __nv_bfloat16* Bh = Al + 64 * AS;
    __nv_bfloat16* Bl = Bh + K * BS;
    float* Dsm = (float*)(smp + 512);

    const int tid = threadIdx.x;
    const int wid = tid >> 5;
    const int m0 = (int)(blockIdx.x >> 2) * 64;
    const int n0 = (int)(blockIdx.x & 3) * 128;

    if (tid < 128) bias[tid] = bih[n0 + tid] + bhh[n0 + tid];

    for (int i = tid; i < 64 * K / 8; i += 256) {
        const int r = i / (K / 8), c8 = (i % (K / 8)) * 8;
        *(uint4*)(Ah + r * AS + c8) =
            *(const uint4*)(Ahg + (size_t)(m0 + r) * K + c8);
        *(uint4*)(Al + r * AS + c8) =
            *(const uint4*)(Alg + (size_t)(m0 + r) * K + c8);
    }
    for (int i = tid; i < K * 16; i += 256) {
        const int k = i >> 4, c8 = (i & 15) * 8;
        *(uint4*)(Bh + k * BS + c8) =
            *(const uint4*)(Bhg + (size_t)k * G4 + n0 + c8);
        *(uint4*)(Bl + k * BS + c8) =
            *(const uint4*)(Blg + (size_t)k * G4 + n0 + c8);
    }
    __syncthreads();

    const int wm = wid >> 1;
    const int wn = wid & 1;

    wmma::fragment<wmma::accumulator, 16, 16, 16, float> acc[4];
#pragma unroll
    for (int ni = 0; ni < 4; ni++) wmma::fill_fragment(acc[ni], 0.0f);

#pragma unroll
    for (int ks = 0; ks < K / 16; ks++) {
        wmma::fragment<wmma::matrix_a, 16, 16, 16, __nv_bfloat16,
                       wmma::row_major> ah, al;
        wmma::load_matrix_sync(ah, Ah + (wm * 16) * AS + ks * 16, AS);
        wmma::load_matrix_sync(al, Al + (wm * 16) * AS + ks * 16, AS);
#pragma unroll
        for (int ni = 0; ni < 4; ni++) {
            wmma::fragment<wmma::matrix_b, 16, 16, 16, __nv_bfloat16,
                           wmma::row_major> bhf, blf;
            wmma::load_matrix_sync(bhf,
                Bh + ks * 16 * BS + wn * 64 + ni * 16, BS);
            wmma::load_matrix_sync(blf,
                Bl + ks * 16 * BS + wn * 64 + ni * 16, BS);
            wmma::mma_sync(acc[ni], ah, bhf, acc[ni]);
            wmma::mma_sync(acc[ni], ah, blf, acc[ni]);
            wmma::mma_sync(acc[ni], al, bhf, acc[ni]);
        }
    }
    __syncthreads();

#pragma unroll
    for (int ni = 0; ni < 4; ni++)
        wmma::store_matrix_sync(
            Dsm + (wm * 16) * 128 + wn * 64 + ni * 16,
            acc[ni], 128, wmma::mem_row_major);
    __syncthreads();

    for (int i = tid; i < 64 * 32; i += 256) {
        const int r = i >> 5, c4 = (i & 31) * 4;
        float4 v = *(const float4*)(Dsm + r * 128 + c4);
        v.x += bias[c4];     v.y += bias[c4 + 1];
        v.z += bias[c4 + 2]; v.w += bias[c4 + 3];
        *(float4*)(pre + (size_t)(m0 + r) * G4 + n0 + c4) = v;
    }
}

// ============================================================================
// lstm_rec chunk, HALF-FOOTPRINT: 128 CTAs x 256 threads, cluster of 4,
// 8 batch rows per cluster. Two-pass dots (rows 0-3, 4-7) reuse acc regs.
// Same validated own/peer + barrier.cluster structure. Two layers' rec
// kernels co-reside (256 CTAs <= 296 slots) -> genuine pipeline overlap.
// ============================================================================
__global__ void __launch_bounds__(256, 2) __cluster_dims__(4, 1, 1)
lstm_rec(const float* __restrict__ pre,   // chunk base [TC,B,512]
         float* __restrict__ out,         // chunk base [TC,B,128]
         const float* __restrict__ Whh,   // [512,128]
         __nv_bfloat16* __restrict__ gh,
         __nv_bfloat16* __restrict__ gl,
         float* __restrict__ hst,         // [B,128] carry
         float* __restrict__ cst,         // [B,128] carry
         int first)
{
    __shared__ float gbuf[8][8][128];                // [slice][b][4g*32j]
    __shared__ __align__(16) float hs[2][8][128];

    const int tid = threadIdx.x, lane = tid & 31, w = tid >> 5;
    uint32_t rank;
    asm("mov.u32 %0, %%cluster_ctarank;" : "=r"(rank));
    const int sl = (w + 2 * (int)rank) & 7;
    const int k0 = sl * 16;
    const bool own = (w < 2);
    const int b0 = (blockIdx.x >> 2) * 8;            // 8 rows / cluster

    unsigned long long Wr[4][8];
#pragma unroll
    for (int g = 0; g < 4; g++) {
        const int grow = g * H_D + (int)rank * 32 + lane;
#pragma unroll
        for (int i = 0; i < 8; i++)
            Wr[g][i] = pack2(Whh[grow * H_D + k0 + 2 * i],
                             Whh[grow * H_D + k0 + 2 * i + 1]);
    }

    // epilogue identity: ALL 256 threads, cell (ob 0..7, oj)
    const int ob = tid >> 5, oj = tid & 31;
    const int jglob = (int)rank * 32 + oj;
    float c_state = 0.0f;
    const float* pre_p = pre + ((size_t)b0 + ob) * G4 + jglob;
    float* out_p = out + ((size_t)b0 + ob) * H_D + jglob;
    __nv_bfloat16* gh_p = gh + ((size_t)b0 + ob) * H_D + jglob;
    __nv_bfloat16* gl_p = gl + ((size_t)b0 + ob) * H_D + jglob;

    if (first) {
        for (int i = tid; i < 8 * H_D; i += 256) hs[0][i >> 7][i & 127] = 0.0f;
    } else {
        for (int i = tid; i < 8 * H_D; i += 256)
            hs[0][i >> 7][i & 127] = hst[(size_t)(b0 + (i >> 7)) * H_D + (i & 127)];
        c_state = cst[(size_t)(b0 + ob) * H_D + jglob];
    }
    __syncthreads();
    asm volatile("barrier.cluster.arrive.aligned;" ::: "memory");

    for (int tl = 0; tl < TC; tl++) {
        const int cur = tl & 1, nxt = cur ^ 1;
        const bool more = (tl + 1 < TC);

        const float p0 = pre_p[0],   p1 = pre_p[128];
        const float p2 = pre_p[256], p3 = pre_p[384];
        pre_p += (size_t)B_SZ * G4;

        if (own) {   // local h columns: ordered by trailing __syncthreads
#pragma unroll
            for (int pass = 0; pass < 2; pass++) {
                unsigned long long acc[4][4];
#pragma unroll
                for (int g = 0; g < 4; g++)
#pragma unroll
                    for (int b = 0; b < 4; b++) acc[g][b] = 0ull;
#pragma unroll
                for (int kk = 0; kk < 4; kk++) {
                    ulonglong2 v[4];
#pragma unroll
                    for (int b = 0; b < 4; b++)
                        v[b] = *(const ulonglong2*)(&hs[cur][pass * 4 + b][k0 + 4 * kk]);
#pragma unroll
                    for (int g = 0; g < 4; g++)
#pragma unroll
                        for (int b = 0; b < 4; b++) {
                            fma2(acc[g][b], v[b].x, Wr[g][2 * kk]);
                            fma2(acc[g][b], v[b].y, Wr[g][2 * kk + 1]);
                        }
                }
#pragma unroll
                for (int g = 0; g < 4; g++)
#pragma unroll
                    for (int b = 0; b < 4; b++)
                        gbuf[sl][pass * 4 + b][g * 32 + lane] = sum2(acc[g][b]);
            }
        }

        asm volatile("barrier.cluster.wait.aligned;" ::: "memory");

        if (!own) {  // peer h columns (DSMEM-published before the barrier)
#pragma unroll
            for (int pass = 0; pass < 2; pass++) {
                unsigned long long acc[4][4];
#pragma unroll
                for (int g = 0; g < 4; g++)
#pragma unroll
                    for (int b = 0; b < 4; b++) acc[g][b] = 0ull;
#pragma unroll
                for (int kk = 0; kk < 4; kk++) {
                    ulonglong2 v[4];
#pragma unroll
                    for (int b = 0; b < 4; b++)
                        v[b] = *(const ulonglong2*)(&hs[cur][pass * 4 + b][k0 + 4 * kk]);
#pragma unroll
                    for (int g = 0; g < 4; g++)
#pragma unroll
                        for (int b = 0; b < 4; b++) {
                            fma2(acc[g][b], v[b].x, Wr[g][2 * kk]);
                            fma2(acc[g][b], v[b].y, Wr[g][2 * kk + 1]);
                        }
                }
#pragma unroll
                for (int g = 0; g < 4; g++)
#pragma unroll
                    for (int b = 0; b < 4; b++)
                        gbuf[sl][pass * 4 + b][g * 32 + lane] = sum2(acc[g][b]);
            }
        }

        __syncthreads();

        {
            float gv0 = p0, gv1 = p1, gv2 = p2, gv3 = p3;
#pragma unroll
            for (int q = 0; q < 8; q++) {
                gv0 += gbuf[q][ob][oj];
                gv1 += gbuf[q][ob][32 + oj];
                gv2 += gbuf[q][ob][64 + oj];
                gv3 += gbuf[q][ob][96 + oj];
            }
            const float ig = fsig(gv0), fg = fsig(gv1);
            const float gg = ftanh(gv2), og = fsig(gv3);
            c_state = fg * c_state + ig * gg;
            const float h = og * ftanh(c_state);

            if (more) {
                float* hp = &hs[nxt][ob][jglob];
                *hp = h;
                const uint32_t la = (uint32_t)__cvta_generic_to_shared(hp);
#pragma unroll
                for (int pr = 0; pr < 4; pr++)
                    if (pr != (int)rank)
                        asm volatile("{ .reg .b32 ra;\n\t"
                            "mapa.shared::cluster.u32 ra, %0, %1;\n\t"
                            "st.shared::cluster.f32 [ra], %2; }"
                            :: "r"(la), "r"(pr), "f"(h) : "memory");
            } else {
                hst[(size_t)(b0 + ob) * H_D + jglob] = h;
                cst[(size_t)(b0 + ob) * H_D + jglob] = c_state;
            }
            *out_p = h;
            out_p += (size_t)B_SZ * H_D;
            const __nv_bfloat16 hh = __float2bfloat16_rn(h);
            *gh_p = hh;
            *gl_p = __float2bfloat16_rn(h - __bfloat162float(hh));
            gh_p += (size_t)B_SZ * H_D;
            gl_p += (size_t)B_SZ * H_D;
        }

        if (more)
            asm volatile("barrier.cluster.arrive.aligned;" ::: "memory");
        __syncthreads();
    }
}

// ============================================================================
// stream/event DAG (created once; capture-legal fork/join each call)
// ============================================================================
struct DagRes {
    cudaStream_t ls[5], lp[5];
    cudaEvent_t fork, evP[5][NCH], evR[5][NCH], tail[10];
    DagRes() {
        for (int l = 0; l < 5; l++) {
            cudaStreamCreateWithFlags(&ls[l], cudaStreamNonBlocking);
            cudaStreamCreateWithFlags(&lp[l], cudaStreamNonBlocking);
        }
        cudaEventCreateWithFlags(&fork, cudaEventDisableTiming);
        for (int l = 0; l < 5; l++)
            for (int c = 0; c < NCH; c++) {
                cudaEventCreateWithFlags(&evP[l][c], cudaEventDisableTiming);
                cudaEventCreateWithFlags(&evR[l][c], cudaEventDisableTiming);
            }
        for (int i = 0; i < 10; i++)
            cudaEventCreateWithFlags(&tail[i], cudaEventDisableTiming);
    }
};
static DagRes g_dag;

extern "C" void kernel_launch(void* const* d_in, const int* in_sizes, int n_in,
                              void* d_out, int out_size) {
    const float* x     = (const float*)d_in[0];
    const float* Wih0  = (const float*)d_in[1];
    const float* Wrest = (const float*)d_in[2];
    const float* Whh   = (const float*)d_in[3];
    const float* bih   = (const float*)d_in[4];
    const float* bhh   = (const float*)d_in[5];
    float* out = (float*)d_out;

    float *bufA, *preb, *hst, *cst;
    __nv_bfloat16 *actH, *actL, *xh, *xl, *wh, *wl;
    cudaGetSymbolAddress((void**)&bufA, g_bufA);
    cudaGetSymbolAddress((void**)&preb, g_preb);
    cudaGetSymbolAddress((void**)&actH, g_actH);
    cudaGetSymbolAddress((void**)&actL, g_actL);
    cudaGetSymbolAddress((void**)&xh, g_xh);
    cudaGetSymbolAddress((void**)&xl, g_xl);
    cudaGetSymbolAddress((void**)&wh, g_wh);
    cudaGetSymbolAddress((void**)&wl, g_wl);
    cudaGetSymbolAddress((void**)&hst, g_hst);
    cudaGetSymbolAddress((void**)&cst, g_cst);

    const int SP64  = 512 + 64 * 72  * 2 * 2 + 64  * 136 * 2 * 2;  //  53760
    const int SP128 = 512 + 64 * 136 * 2 * 2 + 128 * 136 * 2 * 2;  // 104960
    cudaFuncSetAttribute(pregemm<64>,
        cudaFuncAttributeMaxDynamicSharedMemorySize, SP64);
    cudaFuncSetAttribute(pregemm<128>,
        cudaFuncAttributeMaxDynamicSharedMemorySize, SP128);

    DagRes& D = g_dag;

    // ---- upfront conversions on the capture stream ----
    xconvert<<<TB * IN_D / 4 / 256, 256>>>(x, xh, xl, TB * IN_D / 4);
    wconvert<<<64 * G4 / 256, 256>>>(Wih0, wh, wl, 64);
    for (int l = 1; l < 5; l++)
        wconvert<<<128 * G4 / 256, 256>>>(
            Wrest + (size_t)(l - 1) * G4 * H_D,
            wh + (size_t)l * H_D * G4, wl + (size_t)l * H_D * G4, 128);

    cudaEventRecord(D.fork, 0);
    for (int l = 0; l < 5; l++) {
        cudaStreamWaitEvent(D.lp[l], D.fork, 0);
        cudaStreamWaitEvent(D.ls[l], D.fork, 0);
    }

    // ---- pipelined layer-chunk DAG ----
    for (int c = 0; c < NCH; c++) {
        for (int l = 0; l < 5; l++) {
            const size_t rowoff = (size_t)c * CHROWS;
            float* pre_c = preb + ((size_t)l * TB + rowoff) * G4;

            if (l > 0) cudaStreamWaitEvent(D.lp[l], D.evR[l - 1][c], 0);
            if (l == 0) {
                pregemm<64><<<1024, 256, SP64, D.lp[0]>>>(
                    xh + rowoff * IN_D, xl + rowoff * IN_D,
                    wh, wl, bih, bhh, pre_c);
            } else {
                const size_t aoff = ((size_t)(l - 1) * TB + rowoff) * H_D;
                pregemm<128><<<1024, 256, SP128, D.lp[l]>>>(
                    actH + aoff, actL + aoff,
                    wh + (size_t)l * H_D * G4, wl + (size_t)l * H_D * G4,
                    bih + (size_t)l * G4, bhh + (size_t)l * G4, pre_c);
            }
            cudaEventRecord(D.evP[l][c], D.lp[l]);

            cudaStreamWaitEvent(D.ls[l], D.evP[l][c], 0);
            float* out_c = (l == 4) ? out + rowoff * H_D
                                    : bufA + rowoff * H_D;
            const size_t goff = ((size_t)l * TB + rowoff) * H_D;
            lstm_rec<<<128, 256, 0, D.ls[l]>>>(
                pre_c, out_c, Whh + (size_t)l * G4 * H_D,
                actH + goff, actL + goff,
                hst + (size_t)l * B_SZ * H_D, cst + (size_t)l * B_SZ * H_D,
                (c == 0) ? 1 : 0);
            cudaEventRecord(D.evR[l][c], D.ls[l]);
        }
    }

    // ---- join all side streams back to the capture stream ----
    for (int l = 0; l < 5; l++) {
        cudaEventRecord(D.tail[l], D.ls[l]);
        cudaStreamWaitEvent(0, D.tail[l], 0);
        cudaEventRecord(D.tail[5 + l], D.lp[l]);
        cudaStreamWaitEvent(0, D.tail[5 + l], 0);
    }
}